// round 2
// baseline (speedup 1.0000x reference)
#include <cuda_runtime.h>
#include <cuda_bf16.h>
#include <cuda_fp16.h>
#include <cstdint>

// Problem constants
constexpr int N_NODES = 10000;
constexpr int N_EDGES = 100000;
constexpr int WIDTH   = 64;
constexpr int KW      = 1024;   // kernel MLP hidden width
constexpr int KIN     = 6;
constexpr int DEPTH   = 6;

// ---------------------------------------------------------------------------
// Scratch (device globals; no allocations allowed)
// ---------------------------------------------------------------------------
__device__ float  g_h1[(size_t)N_EDGES * KW];                 // 409.6 MB
__device__ float  g_h2[(size_t)N_EDGES * KW];                 // 409.6 MB
__device__ __half g_ew[(size_t)N_EDGES * WIDTH * WIDTH];      // 819.2 MB
__device__ float  g_k2t[KW * KW];                             // tf32-rounded k2
__device__ float  g_k3t[KW * WIDTH * WIDTH];                  // tf32-rounded k3
__device__ float  g_z[N_NODES * WIDTH];
__device__ float  g_zbase[N_NODES * WIDTH];
__device__ float  g_agg[N_NODES * WIDTH];
__device__ float  g_deg[N_NODES];

// ---------------------------------------------------------------------------
// Helpers
// ---------------------------------------------------------------------------
__device__ __forceinline__ float tf32r(float x) {
    uint32_t u;
    asm("cvt.rna.tf32.f32 %0, %1;" : "=r"(u) : "f"(x));
    return __uint_as_float(u);
}

__device__ __forceinline__ void cp16(void* dst, const void* src, bool pred) {
    uint32_t d = (uint32_t)__cvta_generic_to_shared(dst);
    int sz = pred ? 16 : 0;
    asm volatile("cp.async.cg.shared.global [%0], [%1], 16, %2;\n"
                 :: "r"(d), "l"(src), "r"(sz));
}
#define CP_COMMIT() asm volatile("cp.async.commit_group;\n" ::: "memory")
#define CP_WAIT1()  asm volatile("cp.async.wait_group 1;\n" ::: "memory")

__device__ __forceinline__ void mma_tf32(float* c, const uint32_t* a, const uint32_t* b) {
    asm("mma.sync.aligned.m16n8k8.row.col.f32.tf32.tf32.f32 "
        "{%0,%1,%2,%3}, {%4,%5,%6,%7}, {%8,%9}, {%0,%1,%2,%3};"
        : "+f"(c[0]), "+f"(c[1]), "+f"(c[2]), "+f"(c[3])
        : "r"(a[0]), "r"(a[1]), "r"(a[2]), "r"(a[3]), "r"(b[0]), "r"(b[1]));
}

// ---------------------------------------------------------------------------
// Weight prep: round k2/k3 to tf32 once (so GEMM inner loop has no converts)
// ---------------------------------------------------------------------------
__global__ void prep_w(const float* __restrict__ k2, const float* __restrict__ k3) {
    long i = (long)blockIdx.x * blockDim.x + threadIdx.x;
    constexpr long S2 = (long)KW * KW;            // 1,048,576
    constexpr long S3 = (long)KW * WIDTH * WIDTH; // 4,194,304
    if (i < S2)           g_k2t[i]       = tf32r(k2[i]);
    else if (i < S2 + S3) g_k3t[i - S2]  = tf32r(k3[i - S2]);
}

// ---------------------------------------------------------------------------
// h1 = relu(edge_attr @ k1 + b1), stored tf32-rounded fp32.  K=6 -> SIMT.
// Block handles 16 edges x 1024 cols.
// ---------------------------------------------------------------------------
__global__ __launch_bounds__(256) void h1_kernel(const float* __restrict__ ea,
                                                 const float* __restrict__ k1,
                                                 const float* __restrict__ b1) {
    __shared__ float a[16][KIN];
    const int e0 = blockIdx.x * 16;
    const int tid = threadIdx.x;
    if (tid < 16 * KIN) {
        int q = tid / KIN, c = tid % KIN;
        a[q][c] = ea[(long)(e0 + q) * KIN + c];
    }
    __syncthreads();
    #pragma unroll
    for (int jj = 0; jj < 4; jj++) {
        int j = tid + jj * 256;
        float w0 = k1[j],        w1 = k1[KW + j],   w2 = k1[2 * KW + j];
        float w3 = k1[3 * KW + j], w4 = k1[4 * KW + j], w5 = k1[5 * KW + j];
        float bb = b1[j];
        #pragma unroll
        for (int q = 0; q < 16; q++) {
            float s = bb + a[q][0] * w0 + a[q][1] * w1 + a[q][2] * w2
                         + a[q][3] * w3 + a[q][4] * w4 + a[q][5] * w5;
            g_h1[(long)(e0 + q) * KW + j] = tf32r(fmaxf(s, 0.f));
        }
    }
}

// ---------------------------------------------------------------------------
// tf32 tensor-core GEMM.
//   MODE 0: g_h2 = tf32r(relu(g_h1 @ g_k2t + bias))   [E,1024]x[1024,1024]
//   MODE 1: g_ew = half(g_h2 @ g_k3t + bias)          [E,1024]x[1024,4096]
// BM=128 BN=128 BK=16, 256 threads (8 warps as 2x4, warp tile 64x32),
// 2-stage cp.async double buffer. Conflict-free smem: A stride 20, B stride 136.
// ---------------------------------------------------------------------------
template <int MODE>
__global__ __launch_bounds__(256) void gemm_tf32(const float* __restrict__ bias) {
    constexpr int NC = (MODE == 0) ? KW : WIDTH * WIDTH;   // 1024 or 4096
    constexpr long M = N_EDGES;
    constexpr int KT = KW / 16;                            // 64 k-tiles
    const float* __restrict__ A = (MODE == 0) ? g_h1 : g_h2;
    const float* __restrict__ B = (MODE == 0) ? g_k2t : g_k3t;

    __shared__ float As[2][128 * 20];
    __shared__ float Bs[2][16 * 136];

    const int tid  = threadIdx.x;
    const int bm   = blockIdx.x, bn = blockIdx.y;
    const int warp = tid >> 5,  lane = tid & 31;
    const int wm   = warp >> 2, wn = warp & 3;        // 2 x 4 warp grid
    const int gid  = lane >> 2, tig = lane & 3;

    float acc[4][4][4];
    #pragma unroll
    for (int i = 0; i < 4; i++)
        #pragma unroll
        for (int j = 0; j < 4; j++)
            #pragma unroll
            for (int r = 0; r < 4; r++) acc[i][j][r] = 0.f;

    const int ar = tid >> 2, akg = tid & 3;   // A loader: row, k-group
    const int brr = tid >> 5, bc = tid & 31;  // B loader: row, col4

    // prologue: stage 0 <- kt 0
    {
        #pragma unroll
        for (int h = 0; h < 2; h++) {
            int r = ar + h * 64;
            long grow = (long)bm * 128 + r;
            cp16(&As[0][r * 20 + akg * 4], A + grow * KW + akg * 4, grow < M);
        }
        #pragma unroll
        for (int h = 0; h < 2; h++) {
            int rr = brr + h * 8;
            cp16(&Bs[0][rr * 136 + bc * 4], B + (long)rr * NC + (long)bn * 128 + bc * 4, true);
        }
    }
    CP_COMMIT();

    for (int kt = 0; kt < KT; kt++) {
        const int cur = kt & 1;
        if (kt + 1 < KT) {
            const int nkt = kt + 1, nb = cur ^ 1;
            #pragma unroll
            for (int h = 0; h < 2; h++) {
                int r = ar + h * 64;
                long grow = (long)bm * 128 + r;
                cp16(&As[nb][r * 20 + akg * 4], A + grow * KW + nkt * 16 + akg * 4, grow < M);
            }
            #pragma unroll
            for (int h = 0; h < 2; h++) {
                int rr = brr + h * 8;
                cp16(&Bs[nb][rr * 136 + bc * 4],
                     B + (long)(nkt * 16 + rr) * NC + (long)bn * 128 + bc * 4, true);
            }
        }
        CP_COMMIT();
        CP_WAIT1();
        __syncthreads();

        const float* Ab = As[cur];
        const float* Bb = Bs[cur];
        #pragma unroll
        for (int kk = 0; kk < 2; kk++) {
            const int kb = kk * 8;
            uint32_t af[4][4], bfr[4][2];
            #pragma unroll
            for (int mi = 0; mi < 4; mi++) {
                int m = wm * 64 + mi * 16 + gid;
                af[mi][0] = __float_as_uint(Ab[m * 20 + kb + tig]);
                af[mi][1] = __float_as_uint(Ab[(m + 8) * 20 + kb + tig]);
                af[mi][2] = __float_as_uint(Ab[m * 20 + kb + tig + 4]);
                af[mi][3] = __float_as_uint(Ab[(m + 8) * 20 + kb + tig + 4]);
            }
            #pragma unroll
            for (int ni = 0; ni < 4; ni++) {
                int n = wn * 32 + ni * 8 + gid;
                bfr[ni][0] = __float_as_uint(Bb[(kb + tig) * 136 + n]);
                bfr[ni][1] = __float_as_uint(Bb[(kb + tig + 4) * 136 + n]);
            }
            #pragma unroll
            for (int mi = 0; mi < 4; mi++)
                #pragma unroll
                for (int ni = 0; ni < 4; ni++)
                    mma_tf32(acc[mi][ni], af[mi], bfr[ni]);
        }
        __syncthreads();
    }

    // epilogue
    #pragma unroll
    for (int mi = 0; mi < 4; mi++) {
        long r0 = (long)bm * 128 + wm * 64 + mi * 16 + gid;
        #pragma unroll
        for (int ni = 0; ni < 4; ni++) {
            int c0 = bn * 128 + wn * 32 + ni * 8 + tig * 2;
            float bb0 = bias[c0], bb1 = bias[c0 + 1];
            #pragma unroll
            for (int h = 0; h < 2; h++) {
                long r = r0 + h * 8;
                if (r < M) {
                    float v0 = acc[mi][ni][h * 2 + 0] + bb0;
                    float v1 = acc[mi][ni][h * 2 + 1] + bb1;
                    if (MODE == 0) {
                        v0 = tf32r(fmaxf(v0, 0.f));
                        v1 = tf32r(fmaxf(v1, 0.f));
                        *reinterpret_cast<float2*>(&g_h2[r * KW + c0]) = make_float2(v0, v1);
                    } else {
                        *reinterpret_cast<__half2*>(&g_ew[r * (WIDTH * WIDTH) + c0]) =
                            __floats2half2_rn(v0, v1);
                    }
                }
            }
        }
    }
}

// ---------------------------------------------------------------------------
// Degree (scatter count), z0 init
// ---------------------------------------------------------------------------
__global__ void deg_zero() {
    int i = blockIdx.x * 256 + threadIdx.x;
    if (i < N_NODES) g_deg[i] = 0.f;
}
__global__ void deg_count(const int* __restrict__ dst) {
    int e = blockIdx.x * 256 + threadIdx.x;
    if (e < N_EDGES) atomicAdd(&g_deg[dst[e]], 1.f);
}
__global__ void z0_kernel(const float* __restrict__ x, const float* __restrict__ w,
                          const float* __restrict__ b) {
    int i = blockIdx.x * 256 + threadIdx.x;
    if (i < N_NODES * WIDTH) g_z[i] = x[i >> 6] * w[i & 63] + b[i & 63];
}

// ---------------------------------------------------------------------------
// zbase = z @ root_w + conv_b   (also zeroes agg).  4 nodes / 256-thread block.
// ---------------------------------------------------------------------------
__global__ __launch_bounds__(256) void zbase_kernel(const float* __restrict__ rw,
                                                    const float* __restrict__ cb) {
    __shared__ float w[WIDTH * WIDTH];
    __shared__ float zs[4][WIDTH];
    const int tid = threadIdx.x;
    const int n0 = blockIdx.x * 4;
    for (int t = tid; t < WIDTH * WIDTH; t += 256) w[t] = rw[t];
    const int q = tid >> 6, o = tid & 63;
    zs[q][o] = g_z[(n0 + q) * WIDTH + o];
    __syncthreads();
    float s = cb[o];
    #pragma unroll
    for (int i = 0; i < WIDTH; i++) s += zs[q][i] * w[i * WIDTH + o];
    g_zbase[(n0 + q) * WIDTH + o] = s;
    g_agg[(n0 + q) * WIDTH + o] = 0.f;
}

// ---------------------------------------------------------------------------
// Message + scatter: one warp per edge. msg = z[src] @ ew[e] (64x64 fp16),
// fp32 accumulate, atomic scatter-add into agg[dst]. HBM-bound on ew stream.
// ---------------------------------------------------------------------------
__global__ __launch_bounds__(256) void msg_kernel(const int* __restrict__ src,
                                                  const int* __restrict__ dst) {
    const int e = blockIdx.x * 8 + (threadIdx.x >> 5);
    if (e >= N_EDGES) return;
    const int lane = threadIdx.x & 31;
    const int s = src[e];
    const float z0 = g_z[s * WIDTH + lane];
    const float z1 = g_z[s * WIDTH + 32 + lane];
    const __half2* row = reinterpret_cast<const __half2*>(g_ew) + (size_t)e * 2048 + lane;
    float a0 = 0.f, a1 = 0.f;
    #pragma unroll
    for (int i = 0; i < WIDTH; i++) {
        float zi = __shfl_sync(0xffffffffu, (i < 32) ? z0 : z1, i & 31);
        float2 w = __half22float2(row[i * 32]);
        a0 = fmaf(zi, w.x, a0);
        a1 = fmaf(zi, w.y, a1);
    }
    const int d = dst[e];
    atomicAdd(&g_agg[d * WIDTH + lane * 2],     a0);
    atomicAdd(&g_agg[d * WIDTH + lane * 2 + 1], a1);
}

// ---------------------------------------------------------------------------
// z = relu(agg/deg + zbase)
// ---------------------------------------------------------------------------
__global__ void update_kernel() {
    int i = blockIdx.x * 256 + threadIdx.x;
    if (i < N_NODES * WIDTH) {
        float d = fmaxf(g_deg[i >> 6], 1.f);
        g_z[i] = fmaxf(g_agg[i] / d + g_zbase[i], 0.f);
    }
}

// ---------------------------------------------------------------------------
// out = z @ fc2_w + fc2_b : warp per node
// ---------------------------------------------------------------------------
__global__ __launch_bounds__(256) void out_kernel(const float* __restrict__ w,
                                                  const float* __restrict__ b,
                                                  float* __restrict__ out) {
    const int n = blockIdx.x * 8 + (threadIdx.x >> 5);
    const int lane = threadIdx.x & 31;
    if (n >= N_NODES) return;
    float s = g_z[n * WIDTH + lane] * w[lane] + g_z[n * WIDTH + 32 + lane] * w[32 + lane];
    #pragma unroll
    for (int off = 16; off; off >>= 1) s += __shfl_xor_sync(0xffffffffu, s, off);
    if (lane == 0) out[n] = s + b[0];
}

// ---------------------------------------------------------------------------
// Launch
// ---------------------------------------------------------------------------
extern "C" void kernel_launch(void* const* d_in, const int* in_sizes, int n_in,
                              void* d_out, int out_size) {
    const float* x      = (const float*)d_in[0];
    const int*   ei     = (const int*)  d_in[1];
    const float* ea     = (const float*)d_in[2];
    const float* fc1_w  = (const float*)d_in[3];
    const float* fc1_b  = (const float*)d_in[4];
    const float* k1_w   = (const float*)d_in[5];
    const float* k1_b   = (const float*)d_in[6];
    const float* k2_w   = (const float*)d_in[7];
    const float* k2_b   = (const float*)d_in[8];
    const float* k3_w   = (const float*)d_in[9];
    const float* k3_b   = (const float*)d_in[10];
    const float* root_w = (const float*)d_in[11];
    const float* conv_b = (const float*)d_in[12];
    const float* fc2_w  = (const float*)d_in[13];
    const float* fc2_b  = (const float*)d_in[14];
    const int* src = ei;
    const int* dst = ei + N_EDGES;
    float* out = (float*)d_out;

    prep_w<<<20480, 256>>>(k2_w, k3_w);
    h1_kernel<<<N_EDGES / 16, 256>>>(ea, k1_w, k1_b);
    gemm_tf32<0><<<dim3((N_EDGES + 127) / 128, KW / 128), 256>>>(k2_b);
    gemm_tf32<1><<<dim3((N_EDGES + 127) / 128, (WIDTH * WIDTH) / 128), 256>>>(k3_b);
    deg_zero<<<(N_NODES + 255) / 256, 256>>>();
    deg_count<<<(N_EDGES + 255) / 256, 256>>>(dst);
    z0_kernel<<<(N_NODES * WIDTH) / 256, 256>>>(x, fc1_w, fc1_b);
    for (int it = 0; it < DEPTH; it++) {
        zbase_kernel<<<N_NODES / 4, 256>>>(root_w, conv_b);
        msg_kernel<<<(N_EDGES + 7) / 8, 256>>>(src, dst);
        update_kernel<<<(N_NODES * WIDTH) / 256, 256>>>();
    }
    out_kernel<<<(N_NODES + 7) / 8, 256>>>(fc2_w, fc2_b, out);
}

// round 3
// speedup vs baseline: 1.0411x; 1.0411x over previous
#include <cuda_runtime.h>
#include <cuda_bf16.h>
#include <cuda_fp16.h>
#include <cstdint>

// Problem constants
constexpr int N_NODES = 10000;
constexpr int N_EDGES = 100000;
constexpr int WIDTH   = 64;
constexpr int KW      = 1024;
constexpr int KIN     = 6;
constexpr int DEPTH   = 6;

// ---------------------------------------------------------------------------
// Scratch (device globals; no allocations allowed)
// ---------------------------------------------------------------------------
__device__ __half g_h1[(size_t)N_EDGES * KW];                 // 204.8 MB
__device__ __half g_h2[(size_t)N_EDGES * KW];                 // 204.8 MB
__device__ float  g_ew[(size_t)N_EDGES * WIDTH * WIDTH];      // 1638 MB (fp32 for precision)
__device__ __half g_k2t[KW * KW];                             // k2 transposed [N][K]
__device__ __half g_k3t[WIDTH * WIDTH * KW];                  // k3 transposed [N][K]
__device__ float  g_z[N_NODES * WIDTH];
__device__ float  g_zbase[N_NODES * WIDTH];
__device__ float  g_agg[N_NODES * WIDTH];
__device__ float  g_deg[N_NODES];

// ---------------------------------------------------------------------------
// Helpers
// ---------------------------------------------------------------------------
__device__ __forceinline__ void cp16(void* dst, const void* src, bool pred) {
    uint32_t d = (uint32_t)__cvta_generic_to_shared(dst);
    int sz = pred ? 16 : 0;
    asm volatile("cp.async.cg.shared.global [%0], [%1], 16, %2;\n"
                 :: "r"(d), "l"(src), "r"(sz));
}
#define CP_COMMIT() asm volatile("cp.async.commit_group;\n" ::: "memory")
#define CP_WAIT1()  asm volatile("cp.async.wait_group 1;\n" ::: "memory")

__device__ __forceinline__ void ldsm_x4(uint32_t* r, uint32_t addr) {
    asm volatile("ldmatrix.sync.aligned.m8n8.x4.shared.b16 {%0,%1,%2,%3}, [%4];"
                 : "=r"(r[0]), "=r"(r[1]), "=r"(r[2]), "=r"(r[3]) : "r"(addr));
}

__device__ __forceinline__ void mma_f16(float* c, const uint32_t* a, const uint32_t* b) {
    asm("mma.sync.aligned.m16n8k16.row.col.f32.f16.f16.f32 "
        "{%0,%1,%2,%3}, {%4,%5,%6,%7}, {%8,%9}, {%0,%1,%2,%3};"
        : "+f"(c[0]), "+f"(c[1]), "+f"(c[2]), "+f"(c[3])
        : "r"(a[0]), "r"(a[1]), "r"(a[2]), "r"(a[3]), "r"(b[0]), "r"(b[1]));
}

// ---------------------------------------------------------------------------
// Weight prep: transpose k2/k3 to [N][K] and convert to half (tiled via smem)
// ---------------------------------------------------------------------------
__global__ void transpose_h(const float* __restrict__ in, __half* __restrict__ out,
                            int K, int N) {
    __shared__ float t[32][33];
    const int k0 = blockIdx.x * 32, n0 = blockIdx.y * 32;
    const int tx = threadIdx.x, ty = threadIdx.y;   // 32 x 8
    #pragma unroll
    for (int j = 0; j < 32; j += 8)
        t[ty + j][tx] = in[(size_t)(k0 + ty + j) * N + n0 + tx];
    __syncthreads();
    #pragma unroll
    for (int j = 0; j < 32; j += 8)
        out[(size_t)(n0 + ty + j) * K + k0 + tx] = __float2half_rn(t[tx][ty + j]);
}

// ---------------------------------------------------------------------------
// h1 = relu(edge_attr @ k1 + b1), stored half.  K=6 -> SIMT.
// ---------------------------------------------------------------------------
__global__ __launch_bounds__(256) void h1_kernel(const float* __restrict__ ea,
                                                 const float* __restrict__ k1,
                                                 const float* __restrict__ b1) {
    __shared__ float a[16][KIN];
    const int e0 = blockIdx.x * 16;
    const int tid = threadIdx.x;
    if (tid < 16 * KIN) {
        int q = tid / KIN, c = tid % KIN;
        a[q][c] = ea[(long)(e0 + q) * KIN + c];
    }
    __syncthreads();
    #pragma unroll
    for (int jj = 0; jj < 4; jj++) {
        int j = tid + jj * 256;
        float w0 = k1[j],          w1 = k1[KW + j],     w2 = k1[2 * KW + j];
        float w3 = k1[3 * KW + j], w4 = k1[4 * KW + j], w5 = k1[5 * KW + j];
        float bb = b1[j];
        #pragma unroll
        for (int q = 0; q < 16; q++) {
            float s = bb + a[q][0] * w0 + a[q][1] * w1 + a[q][2] * w2
                         + a[q][3] * w3 + a[q][4] * w4 + a[q][5] * w5;
            g_h1[(long)(e0 + q) * KW + j] = __float2half_rn(fmaxf(s, 0.f));
        }
    }
}

// ---------------------------------------------------------------------------
// fp16 tensor-core GEMM, fp32 accumulate.
//   MODE 0: g_h2 = half(relu(g_h1 @ k2 + b2))   [E,1024]x[1024,1024]
//   MODE 1: g_ew = fp32 (g_h2 @ k3 + b3)        [E,1024]x[1024,4096]
// B pre-transposed to [N][K] half. BM=128 BN=128 BK=32, 8 warps (2x4),
// warp tile 64x32. ldmatrix.x4 frags, smem row stride 40 halfs (conflict-free),
// 2-stage cp.async. Grid: blockIdx.x = bn (fast) for L2 reuse of A.
// ---------------------------------------------------------------------------
template <int MODE>
__global__ __launch_bounds__(256, 2) void gemm_f16(const float* __restrict__ bias) {
    constexpr int NC = (MODE == 0) ? KW : WIDTH * WIDTH;   // 1024 or 4096
    constexpr long M = N_EDGES;
    constexpr int KT = KW / 32;                            // 32 k-tiles
    constexpr int LDS = 40;                                // smem row stride (halfs)
    const __half* __restrict__ A  = (MODE == 0) ? g_h1  : g_h2;
    const __half* __restrict__ Bt = (MODE == 0) ? g_k2t : g_k3t;

    __shared__ alignas(16) __half As[2][128 * LDS];
    __shared__ alignas(16) __half Bs[2][128 * LDS];

    const int tid  = threadIdx.x;
    const int bn   = blockIdx.x;          // fast-moving: N tile
    const int bm   = blockIdx.y;          // M tile
    const int warp = tid >> 5, lane = tid & 31;
    const int wm   = warp >> 2, wn = warp & 3;      // 2 x 4 warp grid
    const int gid  = lane >> 2, tig = lane & 3;

    float acc[4][4][4];
    #pragma unroll
    for (int i = 0; i < 4; i++)
        #pragma unroll
        for (int j = 0; j < 4; j++)
            #pragma unroll
            for (int r = 0; r < 4; r++) acc[i][j][r] = 0.f;

    // loaders: 512 16B-chunks per operand per stage, 2 per thread per operand
    const int lr = tid >> 1;              // 0..127 (row)
    const int lc0 = (tid & 1) * 2;        // chunk 0/2  (each thread does c, c+1)

    const uint32_t sA = (uint32_t)__cvta_generic_to_shared(&As[0][0]);
    const uint32_t sB = (uint32_t)__cvta_generic_to_shared(&Bs[0][0]);

    // ldmatrix lane addressing
    const int a_row = wm * 64 + (lane & 15);
    const int a_kc  = (lane >> 4) * 8;
    const int b_row = wn * 32 + (lane & 7) + ((lane >> 4) & 1) * 8;
    const int b_kc  = ((lane >> 3) & 1) * 8;

    auto load_stage = [&](int s, int kt) {
        long arow = (long)bm * 128 + lr;
        const __half* ga = A + arow * KW + kt * 32;
        const __half* gb = Bt + ((long)bn * 128 + lr) * KW + kt * 32;
        __half* wa = &As[s][lr * LDS];
        __half* wb = &Bs[s][lr * LDS];
        bool pa = arow < M;
        cp16(wa + lc0 * 8,       ga + lc0 * 8,       pa);
        cp16(wa + (lc0 + 1) * 8, ga + (lc0 + 1) * 8, pa);
        cp16(wb + lc0 * 8,       gb + lc0 * 8,       true);
        cp16(wb + (lc0 + 1) * 8, gb + (lc0 + 1) * 8, true);
    };

    load_stage(0, 0);
    CP_COMMIT();

    for (int kt = 0; kt < KT; kt++) {
        const int cur = kt & 1;
        if (kt + 1 < KT) load_stage(cur ^ 1, kt + 1);
        CP_COMMIT();
        CP_WAIT1();
        __syncthreads();

        const uint32_t baseA = sA + cur * (128 * LDS * 2);
        const uint32_t baseB = sB + cur * (128 * LDS * 2);
        #pragma unroll
        for (int ks = 0; ks < 2; ks++) {
            uint32_t af[4][4], bf[4][2];
            #pragma unroll
            for (int mi = 0; mi < 4; mi++) {
                uint32_t ad = baseA + 2 * ((a_row + mi * 16) * LDS + ks * 16 + a_kc);
                ldsm_x4(af[mi], ad);
            }
            #pragma unroll
            for (int pp = 0; pp < 2; pp++) {
                uint32_t r[4];
                uint32_t bd = baseB + 2 * ((b_row + pp * 16) * LDS + ks * 16 + b_kc);
                ldsm_x4(r, bd);
                bf[pp * 2][0] = r[0]; bf[pp * 2][1] = r[1];
                bf[pp * 2 + 1][0] = r[2]; bf[pp * 2 + 1][1] = r[3];
            }
            #pragma unroll
            for (int mi = 0; mi < 4; mi++)
                #pragma unroll
                for (int ni = 0; ni < 4; ni++)
                    mma_f16(acc[mi][ni], af[mi], bf[ni]);
        }
        __syncthreads();
    }

    // epilogue (c-frag: rows gid, gid+8; cols 2*tig, 2*tig+1)
    #pragma unroll
    for (int mi = 0; mi < 4; mi++) {
        long r0 = (long)bm * 128 + wm * 64 + mi * 16 + gid;
        #pragma unroll
        for (int ni = 0; ni < 4; ni++) {
            int c0 = bn * 128 + wn * 32 + ni * 8 + tig * 2;
            float bb0 = bias[c0], bb1 = bias[c0 + 1];
            #pragma unroll
            for (int h = 0; h < 2; h++) {
                long r = r0 + h * 8;
                if (r < M) {
                    float v0 = acc[mi][ni][h * 2 + 0] + bb0;
                    float v1 = acc[mi][ni][h * 2 + 1] + bb1;
                    if (MODE == 0) {
                        *reinterpret_cast<__half2*>(&g_h2[r * KW + c0]) =
                            __floats2half2_rn(fmaxf(v0, 0.f), fmaxf(v1, 0.f));
                    } else {
                        *reinterpret_cast<float2*>(&g_ew[r * (WIDTH * WIDTH) + c0]) =
                            make_float2(v0, v1);
                    }
                }
            }
        }
    }
}

// ---------------------------------------------------------------------------
// Degree, z0 init
// ---------------------------------------------------------------------------
__global__ void deg_zero() {
    int i = blockIdx.x * 256 + threadIdx.x;
    if (i < N_NODES) g_deg[i] = 0.f;
}
__global__ void deg_count(const int* __restrict__ dst) {
    int e = blockIdx.x * 256 + threadIdx.x;
    if (e < N_EDGES) atomicAdd(&g_deg[dst[e]], 1.f);
}
__global__ void z0_kernel(const float* __restrict__ x, const float* __restrict__ w,
                          const float* __restrict__ b) {
    int i = blockIdx.x * 256 + threadIdx.x;
    if (i < N_NODES * WIDTH) g_z[i] = x[i >> 6] * w[i & 63] + b[i & 63];
}

// ---------------------------------------------------------------------------
// zbase = z @ root_w + conv_b (also zeroes agg). 4 nodes / 256-thread block.
// ---------------------------------------------------------------------------
__global__ __launch_bounds__(256) void zbase_kernel(const float* __restrict__ rw,
                                                    const float* __restrict__ cb) {
    __shared__ float w[WIDTH * WIDTH];
    __shared__ float zs[4][WIDTH];
    const int tid = threadIdx.x;
    const int n0 = blockIdx.x * 4;
    for (int t = tid; t < WIDTH * WIDTH; t += 256) w[t] = rw[t];
    const int q = tid >> 6, o = tid & 63;
    zs[q][o] = g_z[(n0 + q) * WIDTH + o];
    __syncthreads();
    float s = cb[o];
    #pragma unroll
    for (int i = 0; i < WIDTH; i++) s += zs[q][i] * w[i * WIDTH + o];
    g_zbase[(n0 + q) * WIDTH + o] = s;
    g_agg[(n0 + q) * WIDTH + o] = 0.f;
}

// ---------------------------------------------------------------------------
// Message + scatter: one warp per edge. msg = z[src] @ ew[e] (64x64 fp32),
// atomic scatter-add into agg[dst]. HBM-bound on ew stream.
// ---------------------------------------------------------------------------
__global__ __launch_bounds__(256) void msg_kernel(const int* __restrict__ src,
                                                  const int* __restrict__ dst) {
    const int e = blockIdx.x * 8 + (threadIdx.x >> 5);
    if (e >= N_EDGES) return;
    const int lane = threadIdx.x & 31;
    const int s = src[e];
    const float z0 = g_z[s * WIDTH + lane];
    const float z1 = g_z[s * WIDTH + 32 + lane];
    const float2* row = reinterpret_cast<const float2*>(g_ew) + (size_t)e * 2048 + lane;
    float a0 = 0.f, a1 = 0.f;
    #pragma unroll
    for (int i = 0; i < WIDTH; i++) {
        float zi = __shfl_sync(0xffffffffu, (i < 32) ? z0 : z1, i & 31);
        float2 w = row[i * 32];
        a0 = fmaf(zi, w.x, a0);
        a1 = fmaf(zi, w.y, a1);
    }
    const int d = dst[e];
    atomicAdd(&g_agg[d * WIDTH + lane * 2],     a0);
    atomicAdd(&g_agg[d * WIDTH + lane * 2 + 1], a1);
}

// ---------------------------------------------------------------------------
// z = relu(agg/deg + zbase)
// ---------------------------------------------------------------------------
__global__ void update_kernel() {
    int i = blockIdx.x * 256 + threadIdx.x;
    if (i < N_NODES * WIDTH) {
        float d = fmaxf(g_deg[i >> 6], 1.f);
        g_z[i] = fmaxf(g_agg[i] / d + g_zbase[i], 0.f);
    }
}

// ---------------------------------------------------------------------------
// out = z @ fc2_w + fc2_b : warp per node
// ---------------------------------------------------------------------------
__global__ __launch_bounds__(256) void out_kernel(const float* __restrict__ w,
                                                  const float* __restrict__ b,
                                                  float* __restrict__ out) {
    const int n = blockIdx.x * 8 + (threadIdx.x >> 5);
    const int lane = threadIdx.x & 31;
    if (n >= N_NODES) return;
    float s = g_z[n * WIDTH + lane] * w[lane] + g_z[n * WIDTH + 32 + lane] * w[32 + lane];
    #pragma unroll
    for (int off = 16; off; off >>= 1) s += __shfl_xor_sync(0xffffffffu, s, off);
    if (lane == 0) out[n] = s + b[0];
}

// ---------------------------------------------------------------------------
// Launch
// ---------------------------------------------------------------------------
extern "C" void kernel_launch(void* const* d_in, const int* in_sizes, int n_in,
                              void* d_out, int out_size) {
    const float* x      = (const float*)d_in[0];
    const int*   ei     = (const int*)  d_in[1];
    const float* ea     = (const float*)d_in[2];
    const float* fc1_w  = (const float*)d_in[3];
    const float* fc1_b  = (const float*)d_in[4];
    const float* k1_w   = (const float*)d_in[5];
    const float* k1_b   = (const float*)d_in[6];
    const float* k2_w   = (const float*)d_in[7];
    const float* k2_b   = (const float*)d_in[8];
    const float* k3_w   = (const float*)d_in[9];
    const float* k3_b   = (const float*)d_in[10];
    const float* root_w = (const float*)d_in[11];
    const float* conv_b = (const float*)d_in[12];
    const float* fc2_w  = (const float*)d_in[13];
    const float* fc2_b  = (const float*)d_in[14];
    const int* src = ei;
    const int* dst = ei + N_EDGES;
    float* out = (float*)d_out;

    __half* k2t_p; cudaGetSymbolAddress((void**)&k2t_p, g_k2t);
    __half* k3t_p; cudaGetSymbolAddress((void**)&k3t_p, g_k3t);

    transpose_h<<<dim3(32, 32),  dim3(32, 8)>>>(k2_w, k2t_p, KW, KW);
    transpose_h<<<dim3(32, 128), dim3(32, 8)>>>(k3_w, k3t_p, KW, WIDTH * WIDTH);
    h1_kernel<<<N_EDGES / 16, 256>>>(ea, k1_w, k1_b);
    gemm_f16<0><<<dim3(KW / 128, (N_EDGES + 127) / 128), 256>>>(k2_b);
    gemm_f16<1><<<dim3((WIDTH * WIDTH) / 128, (N_EDGES + 127) / 128), 256>>>(k3_b);
    deg_zero<<<(N_NODES + 255) / 256, 256>>>();
    deg_count<<<(N_EDGES + 255) / 256, 256>>>(dst);
    z0_kernel<<<(N_NODES * WIDTH) / 256, 256>>>(x, fc1_w, fc1_b);
    for (int it = 0; it < DEPTH; it++) {
        zbase_kernel<<<N_NODES / 4, 256>>>(root_w, conv_b);
        msg_kernel<<<(N_EDGES + 7) / 8, 256>>>(src, dst);
        update_kernel<<<(N_NODES * WIDTH) / 256, 256>>>();
    }
    out_kernel<<<(N_NODES + 7) / 8, 256>>>(fc2_w, fc2_b, out);
}

// round 5
// speedup vs baseline: 1.5459x; 1.4849x over previous
#include <cuda_runtime.h>
#include <cuda_bf16.h>
#include <cuda_fp16.h>
#include <cstdint>

// Problem constants
constexpr int N_NODES = 10000;
constexpr int N_EDGES = 100000;
constexpr int WIDTH   = 64;
constexpr int KW      = 1024;
constexpr int KIN     = 6;
constexpr int DEPTH   = 6;

// ---------------------------------------------------------------------------
// Scratch (device globals; no allocations allowed)
// ---------------------------------------------------------------------------
__device__ __half g_h1[(size_t)N_EDGES * KW];                 // 204.8 MB
__device__ __half g_h2[(size_t)N_EDGES * KW];                 // 204.8 MB
__device__ float  g_ew[(size_t)N_EDGES * WIDTH * WIDTH];      // 1638 MB (fp32)
__device__ __half g_k2t[KW * KW];                             // k2^T [N][K]
__device__ __half g_k3t[WIDTH * WIDTH * KW];                  // k3^T [N][K]
__device__ float  g_z[N_NODES * WIDTH];
__device__ float  g_zbase[N_NODES * WIDTH];
__device__ float  g_agg[N_NODES * WIDTH];
__device__ float  g_deg[N_NODES];

// ---------------------------------------------------------------------------
// Helpers
// ---------------------------------------------------------------------------
__device__ __forceinline__ void cp16(void* dst, const void* src, bool pred) {
    uint32_t d = (uint32_t)__cvta_generic_to_shared(dst);
    int sz = pred ? 16 : 0;
    asm volatile("cp.async.cg.shared.global [%0], [%1], 16, %2;\n"
                 :: "r"(d), "l"(src), "r"(sz));
}
#define CP_COMMIT() asm volatile("cp.async.commit_group;\n" ::: "memory")

__device__ __forceinline__ void ldsm_x4(uint32_t* r, uint32_t addr) {
    asm volatile("ldmatrix.sync.aligned.m8n8.x4.shared.b16 {%0,%1,%2,%3}, [%4];"
                 : "=r"(r[0]), "=r"(r[1]), "=r"(r[2]), "=r"(r[3]) : "r"(addr));
}

__device__ __forceinline__ void mma_f16(float* c, const uint32_t* a, const uint32_t* b) {
    asm("mma.sync.aligned.m16n8k16.row.col.f32.f16.f16.f32 "
        "{%0,%1,%2,%3}, {%4,%5,%6,%7}, {%8,%9}, {%0,%1,%2,%3};"
        : "+f"(c[0]), "+f"(c[1]), "+f"(c[2]), "+f"(c[3])
        : "r"(a[0]), "r"(a[1]), "r"(a[2]), "r"(a[3]), "r"(b[0]), "r"(b[1]));
}

// ---------------------------------------------------------------------------
// Weight prep: transpose k2/k3 to [N][K] and convert to half
// ---------------------------------------------------------------------------
__global__ void transpose_h(const float* __restrict__ in, __half* __restrict__ out,
                            int K, int N) {
    __shared__ float t[32][33];
    const int k0 = blockIdx.x * 32, n0 = blockIdx.y * 32;
    const int tx = threadIdx.x, ty = threadIdx.y;   // 32 x 8
    #pragma unroll
    for (int j = 0; j < 32; j += 8)
        t[ty + j][tx] = in[(size_t)(k0 + ty + j) * N + n0 + tx];
    __syncthreads();
    #pragma unroll
    for (int j = 0; j < 32; j += 8)
        out[(size_t)(n0 + ty + j) * K + k0 + tx] = __float2half_rn(t[tx][ty + j]);
}

// ---------------------------------------------------------------------------
// h1 = relu(edge_attr @ k1 + b1), stored half.  K=6 -> SIMT.
// ---------------------------------------------------------------------------
__global__ __launch_bounds__(256) void h1_kernel(const float* __restrict__ ea,
                                                 const float* __restrict__ k1,
                                                 const float* __restrict__ b1) {
    __shared__ float a[16][KIN];
    const int e0 = blockIdx.x * 16;
    const int tid = threadIdx.x;
    if (tid < 16 * KIN) {
        int q = tid / KIN, c = tid % KIN;
        a[q][c] = ea[(long)(e0 + q) * KIN + c];
    }
    __syncthreads();
    #pragma unroll
    for (int jj = 0; jj < 4; jj++) {
        int j = tid + jj * 256;
        float w0 = k1[j],          w1 = k1[KW + j],     w2 = k1[2 * KW + j];
        float w3 = k1[3 * KW + j], w4 = k1[4 * KW + j], w5 = k1[5 * KW + j];
        float bb = b1[j];
        #pragma unroll
        for (int q = 0; q < 16; q++) {
            float s = bb + a[q][0] * w0 + a[q][1] * w1 + a[q][2] * w2
                         + a[q][3] * w3 + a[q][4] * w4 + a[q][5] * w5;
            g_h1[(long)(e0 + q) * KW + j] = __float2half_rn(fmaxf(s, 0.f));
        }
    }
}

// ---------------------------------------------------------------------------
// fp16 tensor-core GEMM, fp32 accumulate. 4-stage cp.async ring buffer,
// ONE __syncthreads per k-tile.
//   MODE 0: g_h2 = half(relu(g_h1 @ k2 + b2))   [E,1024]x[1024,1024]
//   MODE 1: g_ew = fp32 (g_h2 @ k3 + b3)        [E,1024]x[1024,4096]
// B pre-transposed [N][K] half. BM=128 BN=128 BK=32, 8 warps (2x4),
// warp tile 64x32, ldmatrix.x4, smem row stride 40 halfs (conflict-free).
// Grid: blockIdx.x = bn (fast) for L2 reuse of A.
// ---------------------------------------------------------------------------
constexpr int G_STAGES = 4;
constexpr int G_STAGE_HALFS = 128 * 40;                      // per operand per stage
constexpr int G_SMEM_BYTES = G_STAGES * G_STAGE_HALFS * 2 * 2;  // 81920

template <int MODE>
__global__ __launch_bounds__(256, 2) void gemm_f16(const float* __restrict__ bias) {
    constexpr long M = N_EDGES;
    constexpr int KT = KW / 32;                            // 32 k-tiles
    constexpr int LDS = 40;                                // smem row stride (halfs)
    const __half* __restrict__ A  = (MODE == 0) ? g_h1  : g_h2;
    const __half* __restrict__ Bt = (MODE == 0) ? g_k2t : g_k3t;

    extern __shared__ __half dsmem[];
    __half* As = dsmem;                                    // 4 x 5120 halfs
    __half* Bs = dsmem + G_STAGES * G_STAGE_HALFS;

    const int tid  = threadIdx.x;
    const int bn   = blockIdx.x;          // fast-moving: N tile
    const int bm   = blockIdx.y;          // M tile
    const int warp = tid >> 5, lane = tid & 31;
    const int wm   = warp >> 2, wn = warp & 3;      // 2 x 4 warp grid
    const int gid  = lane >> 2, tig = lane & 3;

    float acc[4][4][4];
    #pragma unroll
    for (int i = 0; i < 4; i++)
        #pragma unroll
        for (int j = 0; j < 4; j++)
            #pragma unroll
            for (int r = 0; r < 4; r++) acc[i][j][r] = 0.f;

    // loaders: 512 16B-chunks per operand per stage, 2 per thread per operand
    const int lr  = tid >> 1;             // 0..127 (row)
    const int lc0 = (tid & 1) * 2;        // chunks c, c+1 of 4

    const uint32_t sA = (uint32_t)__cvta_generic_to_shared(As);
    const uint32_t sB = (uint32_t)__cvta_generic_to_shared(Bs);

    // ldmatrix lane addressing
    const int a_row = wm * 64 + (lane & 15);
    const int a_kc  = (lane >> 4) * 8;
    const int b_row = wn * 32 + (lane & 7) + ((lane >> 4) & 1) * 8;
    const int b_kc  = ((lane >> 3) & 1) * 8;

    const long m0 = (long)bm * 128;
    const long arow = m0 + lr;
    const bool pa = arow < M;
    const __half* gA = A + arow * KW;
    const __half* gB = Bt + ((long)bn * 128 + lr) * KW;
    __half* wA = As + lr * LDS;
    __half* wB = Bs + lr * LDS;

    auto load_stage = [&](int s, int kt) {
        const __half* ga = gA + kt * 32;
        const __half* gb = gB + kt * 32;
        __half* wa = wA + s * G_STAGE_HALFS;
        __half* wb = wB + s * G_STAGE_HALFS;
        cp16(wa + lc0 * 8,       ga + lc0 * 8,       pa);
        cp16(wa + (lc0 + 1) * 8, ga + (lc0 + 1) * 8, pa);
        cp16(wb + lc0 * 8,       gb + lc0 * 8,       true);
        cp16(wb + (lc0 + 1) * 8, gb + (lc0 + 1) * 8, true);
    };

    // prologue: stages 0..2
    #pragma unroll
    for (int p = 0; p < G_STAGES - 1; p++) {
        load_stage(p, p);
        CP_COMMIT();
    }

    for (int kt = 0; kt < KT; kt++) {
        asm volatile("cp.async.wait_group %0;" :: "n"(G_STAGES - 2) : "memory");
        __syncthreads();

        // issue loads for kt+3 into slot (kt+3)%4 == (kt-1)%4 (freed by the
        // barrier above: all warps finished computing kt-1)
        const int ld_kt = kt + G_STAGES - 1;
        if (ld_kt < KT) load_stage(ld_kt & (G_STAGES - 1), ld_kt);
        CP_COMMIT();

        const int cur = kt & (G_STAGES - 1);
        const uint32_t baseA = sA + cur * (G_STAGE_HALFS * 2);
        const uint32_t baseB = sB + cur * (G_STAGE_HALFS * 2);
        #pragma unroll
        for (int ks = 0; ks < 2; ks++) {
            uint32_t af[4][4], bf[4][2];
            #pragma unroll
            for (int mi = 0; mi < 4; mi++) {
                uint32_t ad = baseA + 2 * ((a_row + mi * 16) * LDS + ks * 16 + a_kc);
                ldsm_x4(af[mi], ad);
            }
            #pragma unroll
            for (int pp = 0; pp < 2; pp++) {
                uint32_t r[4];
                uint32_t bd = baseB + 2 * ((b_row + pp * 16) * LDS + ks * 16 + b_kc);
                ldsm_x4(r, bd);
                bf[pp * 2][0] = r[0]; bf[pp * 2][1] = r[1];
                bf[pp * 2 + 1][0] = r[2]; bf[pp * 2 + 1][1] = r[3];
            }
            #pragma unroll
            for (int mi = 0; mi < 4; mi++)
                #pragma unroll
                for (int ni = 0; ni < 4; ni++)
                    mma_f16(acc[mi][ni], af[mi], bf[ni]);
        }
    }

    // epilogue (c-frag: rows gid, gid+8; cols 2*tig, 2*tig+1)
    #pragma unroll
    for (int mi = 0; mi < 4; mi++) {
        long r0 = m0 + wm * 64 + mi * 16 + gid;
        #pragma unroll
        for (int ni = 0; ni < 4; ni++) {
            int c0 = bn * 128 + wn * 32 + ni * 8 + tig * 2;
            float bb0 = bias[c0], bb1 = bias[c0 + 1];
            #pragma unroll
            for (int h = 0; h < 2; h++) {
                long r = r0 + h * 8;
                if (r < M) {
                    float v0 = acc[mi][ni][h * 2 + 0] + bb0;
                    float v1 = acc[mi][ni][h * 2 + 1] + bb1;
                    if (MODE == 0) {
                        *reinterpret_cast<__half2*>(&g_h2[r * KW + c0]) =
                            __floats2half2_rn(fmaxf(v0, 0.f), fmaxf(v1, 0.f));
                    } else {
                        *reinterpret_cast<float2*>(&g_ew[r * (size_t)(WIDTH * WIDTH) + c0]) =
                            make_float2(v0, v1);
                    }
                }
            }
        }
    }
}

// ---------------------------------------------------------------------------
// Degree, z0 init
// ---------------------------------------------------------------------------
__global__ void deg_zero() {
    int i = blockIdx.x * 256 + threadIdx.x;
    if (i < N_NODES) g_deg[i] = 0.f;
}
__global__ void deg_count(const int* __restrict__ dst) {
    int e = blockIdx.x * 256 + threadIdx.x;
    if (e < N_EDGES) atomicAdd(&g_deg[dst[e]], 1.f);
}
__global__ void z0_kernel(const float* __restrict__ x, const float* __restrict__ w,
                          const float* __restrict__ b) {
    int i = blockIdx.x * 256 + threadIdx.x;
    if (i < N_NODES * WIDTH) g_z[i] = x[i >> 6] * w[i & 63] + b[i & 63];
}

// ---------------------------------------------------------------------------
// zbase = z @ root_w + conv_b (also zeroes agg). 4 nodes / 256-thread block.
// ---------------------------------------------------------------------------
__global__ __launch_bounds__(256) void zbase_kernel(const float* __restrict__ rw,
                                                    const float* __restrict__ cb) {
    __shared__ float w[WIDTH * WIDTH];
    __shared__ float zs[4][WIDTH];
    const int tid = threadIdx.x;
    const int n0 = blockIdx.x * 4;
    for (int t = tid; t < WIDTH * WIDTH; t += 256) w[t] = rw[t];
    const int q = tid >> 6, o = tid & 63;
    zs[q][o] = g_z[(n0 + q) * WIDTH + o];
    __syncthreads();
    float s = cb[o];
    #pragma unroll
    for (int i = 0; i < WIDTH; i++) s += zs[q][i] * w[i * WIDTH + o];
    g_zbase[(n0 + q) * WIDTH + o] = s;
    g_agg[(n0 + q) * WIDTH + o] = 0.f;
}

// ---------------------------------------------------------------------------
// Message + scatter: one warp per edge. msg = z[src] @ ew[e] (64x64 fp32),
// atomic scatter-add into agg[dst]. HBM-bound on ew stream.
// ---------------------------------------------------------------------------
__global__ __launch_bounds__(256) void msg_kernel(const int* __restrict__ src,
                                                  const int* __restrict__ dst) {
    const int e = blockIdx.x * 8 + (threadIdx.x >> 5);
    if (e >= N_EDGES) return;
    const int lane = threadIdx.x & 31;
    const int s = src[e];
    const float z0 = g_z[s * WIDTH + lane];
    const float z1 = g_z[s * WIDTH + 32 + lane];
    const float2* row = reinterpret_cast<const float2*>(g_ew) + (size_t)e * 2048 + lane;
    float a0 = 0.f, a1 = 0.f;
    #pragma unroll
    for (int i = 0; i < WIDTH; i++) {
        float zi = __shfl_sync(0xffffffffu, (i < 32) ? z0 : z1, i & 31);
        float2 w = __ldg(&row[i * 32]);
        a0 = fmaf(zi, w.x, a0);
        a1 = fmaf(zi, w.y, a1);
    }
    const int d = dst[e];
    atomicAdd(&g_agg[d * WIDTH + lane * 2],     a0);
    atomicAdd(&g_agg[d * WIDTH + lane * 2 + 1], a1);
}

// ---------------------------------------------------------------------------
// z = relu(agg/deg + zbase)
// ---------------------------------------------------------------------------
__global__ void update_kernel() {
    int i = blockIdx.x * 256 + threadIdx.x;
    if (i < N_NODES * WIDTH) {
        float d = fmaxf(g_deg[i >> 6], 1.f);
        g_z[i] = fmaxf(g_agg[i] / d + g_zbase[i], 0.f);
    }
}

// ---------------------------------------------------------------------------
// out = z @ fc2_w + fc2_b : warp per node
// ---------------------------------------------------------------------------
__global__ __launch_bounds__(256) void out_kernel(const float* __restrict__ w,
                                                  const float* __restrict__ b,
                                                  float* __restrict__ out) {
    const int n = blockIdx.x * 8 + (threadIdx.x >> 5);
    const int lane = threadIdx.x & 31;
    if (n >= N_NODES) return;
    float s = g_z[n * WIDTH + lane] * w[lane] + g_z[n * WIDTH + 32 + lane] * w[32 + lane];
    #pragma unroll
    for (int off = 16; off; off >>= 1) s += __shfl_xor_sync(0xffffffffu, s, off);
    if (lane == 0) out[n] = s + b[0];
}

// ---------------------------------------------------------------------------
// Launch
// ---------------------------------------------------------------------------
extern "C" void kernel_launch(void* const* d_in, const int* in_sizes, int n_in,
                              void* d_out, int out_size) {
    const float* x      = (const float*)d_in[0];
    const int*   ei     = (const int*)  d_in[1];
    const float* ea     = (const float*)d_in[2];
    const float* fc1_w  = (const float*)d_in[3];
    const float* fc1_b  = (const float*)d_in[4];
    const float* k1_w   = (const float*)d_in[5];
    const float* k1_b   = (const float*)d_in[6];
    const float* k2_w   = (const float*)d_in[7];
    const float* k2_b   = (const float*)d_in[8];
    const float* k3_w   = (const float*)d_in[9];
    const float* k3_b   = (const float*)d_in[10];
    const float* root_w = (const float*)d_in[11];
    const float* conv_b = (const float*)d_in[12];
    const float* fc2_w  = (const float*)d_in[13];
    const float* fc2_b  = (const float*)d_in[14];
    const int* src = ei;
    const int* dst = ei + N_EDGES;
    float* out = (float*)d_out;

    __half* k2t_p; cudaGetSymbolAddress((void**)&k2t_p, g_k2t);
    __half* k3t_p; cudaGetSymbolAddress((void**)&k3t_p, g_k3t);

    cudaFuncSetAttribute(gemm_f16<0>, cudaFuncAttributeMaxDynamicSharedMemorySize, G_SMEM_BYTES);
    cudaFuncSetAttribute(gemm_f16<1>, cudaFuncAttributeMaxDynamicSharedMemorySize, G_SMEM_BYTES);

    transpose_h<<<dim3(32, 32),  dim3(32, 8)>>>(k2_w, k2t_p, KW, KW);
    transpose_h<<<dim3(32, 128), dim3(32, 8)>>>(k3_w, k3t_p, KW, WIDTH * WIDTH);
    h1_kernel<<<N_EDGES / 16, 256>>>(ea, k1_w, k1_b);
    gemm_f16<0><<<dim3(KW / 128, (N_EDGES + 127) / 128), 256, G_SMEM_BYTES>>>(k2_b);
    gemm_f16<1><<<dim3((WIDTH * WIDTH) / 128, (N_EDGES + 127) / 128), 256, G_SMEM_BYTES>>>(k3_b);
    deg_zero<<<(N_NODES + 255) / 256, 256>>>();
    deg_count<<<(N_EDGES + 255) / 256, 256>>>(dst);
    z0_kernel<<<(N_NODES * WIDTH) / 256, 256>>>(x, fc1_w, fc1_b);
    for (int it = 0; it < DEPTH; it++) {
        zbase_kernel<<<N_NODES / 4, 256>>>(root_w, conv_b);
        msg_kernel<<<(N_EDGES + 7) / 8, 256>>>(src, dst);
        update_kernel<<<(N_NODES * WIDTH) / 256, 256>>>();
    }
    out_kernel<<<(N_NODES + 7) / 8, 256>>>(fc2_w, fc2_b, out);
}

// round 6
// speedup vs baseline: 1.5685x; 1.0146x over previous
#include <cuda_runtime.h>
#include <cuda_bf16.h>
#include <cuda_fp16.h>
#include <cstdint>

// Problem constants
constexpr int N_NODES = 10000;
constexpr int N_EDGES = 100000;
constexpr int WIDTH   = 64;
constexpr int KW      = 1024;
constexpr int KIN     = 6;
constexpr int DEPTH   = 6;

// ---------------------------------------------------------------------------
// Scratch (device globals; no allocations allowed)
// ---------------------------------------------------------------------------
__device__ __half g_h1[(size_t)N_EDGES * KW];                 // 204.8 MB
__device__ __half g_h2[(size_t)N_EDGES * KW];                 // 204.8 MB
__device__ __half g_ew[(size_t)N_EDGES * WIDTH * WIDTH];      // 819.2 MB (fp16: R2 evidence says no extra error)
__device__ __half g_k2t[KW * KW];                             // k2^T [N][K]
__device__ __half g_k3t[WIDTH * WIDTH * KW];                  // k3^T [N][K]
__device__ float  g_z[N_NODES * WIDTH];
__device__ float  g_zbase[N_NODES * WIDTH];
__device__ float  g_agg[N_NODES * WIDTH];
__device__ float  g_deg[N_NODES];

// ---------------------------------------------------------------------------
// Helpers
// ---------------------------------------------------------------------------
__device__ __forceinline__ void cp16(void* dst, const void* src, bool pred) {
    uint32_t d = (uint32_t)__cvta_generic_to_shared(dst);
    int sz = pred ? 16 : 0;
    asm volatile("cp.async.cg.shared.global [%0], [%1], 16, %2;\n"
                 :: "r"(d), "l"(src), "r"(sz));
}
#define CP_COMMIT() asm volatile("cp.async.commit_group;\n" ::: "memory")

__device__ __forceinline__ void ldsm_x4(uint32_t* r, uint32_t addr) {
    asm volatile("ldmatrix.sync.aligned.m8n8.x4.shared.b16 {%0,%1,%2,%3}, [%4];"
                 : "=r"(r[0]), "=r"(r[1]), "=r"(r[2]), "=r"(r[3]) : "r"(addr));
}

__device__ __forceinline__ void mma_f16(float* c, const uint32_t* a, const uint32_t* b) {
    asm("mma.sync.aligned.m16n8k16.row.col.f32.f16.f16.f32 "
        "{%0,%1,%2,%3}, {%4,%5,%6,%7}, {%8,%9}, {%0,%1,%2,%3};"
        : "+f"(c[0]), "+f"(c[1]), "+f"(c[2]), "+f"(c[3])
        : "r"(a[0]), "r"(a[1]), "r"(a[2]), "r"(a[3]), "r"(b[0]), "r"(b[1]));
}

// ---------------------------------------------------------------------------
// Weight prep: transpose k2/k3 to [N][K] and convert to half
// ---------------------------------------------------------------------------
__global__ void transpose_h(const float* __restrict__ in, __half* __restrict__ out,
                            int K, int N) {
    __shared__ float t[32][33];
    const int k0 = blockIdx.x * 32, n0 = blockIdx.y * 32;
    const int tx = threadIdx.x, ty = threadIdx.y;   // 32 x 8
    #pragma unroll
    for (int j = 0; j < 32; j += 8)
        t[ty + j][tx] = in[(size_t)(k0 + ty + j) * N + n0 + tx];
    __syncthreads();
    #pragma unroll
    for (int j = 0; j < 32; j += 8)
        out[(size_t)(n0 + ty + j) * K + k0 + tx] = __float2half_rn(t[tx][ty + j]);
}

// ---------------------------------------------------------------------------
// h1 = relu(edge_attr @ k1 + b1), stored half.  K=6 -> SIMT.
// ---------------------------------------------------------------------------
__global__ __launch_bounds__(256) void h1_kernel(const float* __restrict__ ea,
                                                 const float* __restrict__ k1,
                                                 const float* __restrict__ b1) {
    __shared__ float a[16][KIN];
    const int e0 = blockIdx.x * 16;
    const int tid = threadIdx.x;
    if (tid < 16 * KIN) {
        int q = tid / KIN, c = tid % KIN;
        a[q][c] = ea[(long)(e0 + q) * KIN + c];
    }
    __syncthreads();
    #pragma unroll
    for (int jj = 0; jj < 4; jj++) {
        int j = tid + jj * 256;
        float w0 = k1[j],          w1 = k1[KW + j],     w2 = k1[2 * KW + j];
        float w3 = k1[3 * KW + j], w4 = k1[4 * KW + j], w5 = k1[5 * KW + j];
        float bb = b1[j];
        #pragma unroll
        for (int q = 0; q < 16; q++) {
            float s = bb + a[q][0] * w0 + a[q][1] * w1 + a[q][2] * w2
                         + a[q][3] * w3 + a[q][4] * w4 + a[q][5] * w5;
            g_h1[(long)(e0 + q) * KW + j] = __float2half_rn(fmaxf(s, 0.f));
        }
    }
}

// ---------------------------------------------------------------------------
// fp16 tensor-core GEMM, fp32 accumulate. 4-stage cp.async ring buffer,
// ONE __syncthreads per k-tile.
//   MODE 0: g_h2 = half(relu(g_h1 @ k2 + b2))   [E,1024]x[1024,1024]
//   MODE 1: g_ew = half(g_h2 @ k3 + b3)         [E,1024]x[1024,4096]
// B pre-transposed [N][K] half. BM=128 BN=128 BK=32, 8 warps (2x4),
// warp tile 64x32, ldmatrix.x4, smem row stride 40 halfs (conflict-free).
// Grid: blockIdx.x = bn (fast) for L2 reuse of A.
// ---------------------------------------------------------------------------
constexpr int G_STAGES = 4;
constexpr int G_STAGE_HALFS = 128 * 40;                      // per operand per stage
constexpr int G_SMEM_BYTES = G_STAGES * G_STAGE_HALFS * 2 * 2;  // 81920

template <int MODE>
__global__ __launch_bounds__(256, 2) void gemm_f16(const float* __restrict__ bias) {
    constexpr long M = N_EDGES;
    constexpr int KT = KW / 32;                            // 32 k-tiles
    constexpr int LDS = 40;                                // smem row stride (halfs)
    const __half* __restrict__ A  = (MODE == 0) ? g_h1  : g_h2;
    const __half* __restrict__ Bt = (MODE == 0) ? g_k2t : g_k3t;

    extern __shared__ __half dsmem[];
    __half* As = dsmem;                                    // 4 x 5120 halfs
    __half* Bs = dsmem + G_STAGES * G_STAGE_HALFS;

    const int tid  = threadIdx.x;
    const int bn   = blockIdx.x;          // fast-moving: N tile
    const int bm   = blockIdx.y;          // M tile
    const int warp = tid >> 5, lane = tid & 31;
    const int wm   = warp >> 2, wn = warp & 3;      // 2 x 4 warp grid
    const int gid  = lane >> 2, tig = lane & 3;

    float acc[4][4][4];
    #pragma unroll
    for (int i = 0; i < 4; i++)
        #pragma unroll
        for (int j = 0; j < 4; j++)
            #pragma unroll
            for (int r = 0; r < 4; r++) acc[i][j][r] = 0.f;

    // loaders: 512 16B-chunks per operand per stage, 2 per thread per operand
    const int lr  = tid >> 1;             // 0..127 (row)
    const int lc0 = (tid & 1) * 2;        // chunks c, c+1 of 4

    const uint32_t sA = (uint32_t)__cvta_generic_to_shared(As);
    const uint32_t sB = (uint32_t)__cvta_generic_to_shared(Bs);

    // ldmatrix lane addressing
    const int a_row = wm * 64 + (lane & 15);
    const int a_kc  = (lane >> 4) * 8;
    const int b_row = wn * 32 + (lane & 7) + ((lane >> 4) & 1) * 8;
    const int b_kc  = ((lane >> 3) & 1) * 8;

    const long m0 = (long)bm * 128;
    const long arow = m0 + lr;
    const bool pa = arow < M;
    const __half* gA = A + arow * KW;
    const __half* gB = Bt + ((long)bn * 128 + lr) * KW;
    __half* wA = As + lr * LDS;
    __half* wB = Bs + lr * LDS;

    auto load_stage = [&](int s, int kt) {
        const __half* ga = gA + kt * 32;
        const __half* gb = gB + kt * 32;
        __half* wa = wA + s * G_STAGE_HALFS;
        __half* wb = wB + s * G_STAGE_HALFS;
        cp16(wa + lc0 * 8,       ga + lc0 * 8,       pa);
        cp16(wa + (lc0 + 1) * 8, ga + (lc0 + 1) * 8, pa);
        cp16(wb + lc0 * 8,       gb + lc0 * 8,       true);
        cp16(wb + (lc0 + 1) * 8, gb + (lc0 + 1) * 8, true);
    };

    // prologue: stages 0..2
    #pragma unroll
    for (int p = 0; p < G_STAGES - 1; p++) {
        load_stage(p, p);
        CP_COMMIT();
    }

    for (int kt = 0; kt < KT; kt++) {
        asm volatile("cp.async.wait_group %0;" :: "n"(G_STAGES - 2) : "memory");
        __syncthreads();

        // issue loads for kt+3 into slot (kt+3)%4 == (kt-1)%4 (freed by the
        // barrier above: all warps finished computing kt-1)
        const int ld_kt = kt + G_STAGES - 1;
        if (ld_kt < KT) load_stage(ld_kt & (G_STAGES - 1), ld_kt);
        CP_COMMIT();

        const int cur = kt & (G_STAGES - 1);
        const uint32_t baseA = sA + cur * (G_STAGE_HALFS * 2);
        const uint32_t baseB = sB + cur * (G_STAGE_HALFS * 2);
        #pragma unroll
        for (int ks = 0; ks < 2; ks++) {
            uint32_t af[4][4], bf[4][2];
            #pragma unroll
            for (int mi = 0; mi < 4; mi++) {
                uint32_t ad = baseA + 2 * ((a_row + mi * 16) * LDS + ks * 16 + a_kc);
                ldsm_x4(af[mi], ad);
            }
            #pragma unroll
            for (int pp = 0; pp < 2; pp++) {
                uint32_t r[4];
                uint32_t bd = baseB + 2 * ((b_row + pp * 16) * LDS + ks * 16 + b_kc);
                ldsm_x4(r, bd);
                bf[pp * 2][0] = r[0]; bf[pp * 2][1] = r[1];
                bf[pp * 2 + 1][0] = r[2]; bf[pp * 2 + 1][1] = r[3];
            }
            #pragma unroll
            for (int mi = 0; mi < 4; mi++)
                #pragma unroll
                for (int ni = 0; ni < 4; ni++)
                    mma_f16(acc[mi][ni], af[mi], bf[ni]);
        }
    }

    // epilogue (c-frag: rows gid, gid+8; cols 2*tig, 2*tig+1)
    #pragma unroll
    for (int mi = 0; mi < 4; mi++) {
        long r0 = m0 + wm * 64 + mi * 16 + gid;
        #pragma unroll
        for (int ni = 0; ni < 4; ni++) {
            int c0 = bn * 128 + wn * 32 + ni * 8 + tig * 2;
            float bb0 = bias[c0], bb1 = bias[c0 + 1];
            #pragma unroll
            for (int h = 0; h < 2; h++) {
                long r = r0 + h * 8;
                if (r < M) {
                    float v0 = acc[mi][ni][h * 2 + 0] + bb0;
                    float v1 = acc[mi][ni][h * 2 + 1] + bb1;
                    if (MODE == 0) {
                        *reinterpret_cast<__half2*>(&g_h2[r * KW + c0]) =
                            __floats2half2_rn(fmaxf(v0, 0.f), fmaxf(v1, 0.f));
                    } else {
                        *reinterpret_cast<__half2*>(&g_ew[r * (size_t)(WIDTH * WIDTH) + c0]) =
                            __floats2half2_rn(v0, v1);
                    }
                }
            }
        }
    }
}

// ---------------------------------------------------------------------------
// Degree, z0 init
// ---------------------------------------------------------------------------
__global__ void deg_zero() {
    int i = blockIdx.x * 256 + threadIdx.x;
    if (i < N_NODES) g_deg[i] = 0.f;
}
__global__ void deg_count(const int* __restrict__ dst) {
    int e = blockIdx.x * 256 + threadIdx.x;
    if (e < N_EDGES) atomicAdd(&g_deg[dst[e]], 1.f);
}
__global__ void z0_kernel(const float* __restrict__ x, const float* __restrict__ w,
                          const float* __restrict__ b) {
    int i = blockIdx.x * 256 + threadIdx.x;
    if (i < N_NODES * WIDTH) g_z[i] = x[i >> 6] * w[i & 63] + b[i & 63];
}

// ---------------------------------------------------------------------------
// zbase = z @ root_w + conv_b (also zeroes agg). 4 nodes / 256-thread block.
// ---------------------------------------------------------------------------
__global__ __launch_bounds__(256) void zbase_kernel(const float* __restrict__ rw,
                                                    const float* __restrict__ cb) {
    __shared__ float w[WIDTH * WIDTH];
    __shared__ float zs[4][WIDTH];
    const int tid = threadIdx.x;
    const int n0 = blockIdx.x * 4;
    for (int t = tid; t < WIDTH * WIDTH; t += 256) w[t] = rw[t];
    const int q = tid >> 6, o = tid & 63;
    zs[q][o] = g_z[(n0 + q) * WIDTH + o];
    __syncthreads();
    float s = cb[o];
    #pragma unroll
    for (int i = 0; i < WIDTH; i++) s += zs[q][i] * w[i * WIDTH + o];
    g_zbase[(n0 + q) * WIDTH + o] = s;
    g_agg[(n0 + q) * WIDTH + o] = 0.f;
}

// ---------------------------------------------------------------------------
// Message + scatter: one warp per edge. msg = z[src] @ ew[e] (64x64 fp16),
// fp32 accumulate, atomic scatter-add into agg[dst]. HBM-bound on ew stream.
// Zero-skip: rows of ew whose z_i == 0 contribute nothing (bit-exact skip).
// z is a ReLU output -> typically ~half the rows are skipped.
// ---------------------------------------------------------------------------
__global__ __launch_bounds__(256) void msg_kernel(const int* __restrict__ src,
                                                  const int* __restrict__ dst) {
    const int e = blockIdx.x * 8 + (threadIdx.x >> 5);
    if (e >= N_EDGES) return;
    const int lane = threadIdx.x & 31;
    const int s = src[e];
    const float z0 = g_z[s * WIDTH + lane];
    const float z1 = g_z[s * WIDTH + 32 + lane];
    uint32_t m0 = __ballot_sync(0xffffffffu, z0 != 0.f);
    uint32_t m1 = __ballot_sync(0xffffffffu, z1 != 0.f);
    const __half2* row = reinterpret_cast<const __half2*>(g_ew) + (size_t)e * 2048 + lane;
    float a0 = 0.f, a1 = 0.f;
    while (m0) {
        int i = __ffs(m0) - 1; m0 &= m0 - 1;
        float zi = __shfl_sync(0xffffffffu, z0, i);
        float2 w = __half22float2(row[i * 32]);
        a0 = fmaf(zi, w.x, a0);
        a1 = fmaf(zi, w.y, a1);
    }
    while (m1) {
        int i = __ffs(m1) - 1; m1 &= m1 - 1;
        float zi = __shfl_sync(0xffffffffu, z1, i);
        float2 w = __half22float2(row[(i + 32) * 32]);
        a0 = fmaf(zi, w.x, a0);
        a1 = fmaf(zi, w.y, a1);
    }
    const int d = dst[e];
    atomicAdd(&g_agg[d * WIDTH + lane * 2],     a0);
    atomicAdd(&g_agg[d * WIDTH + lane * 2 + 1], a1);
}

// ---------------------------------------------------------------------------
// z = relu(agg/deg + zbase)
// ---------------------------------------------------------------------------
__global__ void update_kernel() {
    int i = blockIdx.x * 256 + threadIdx.x;
    if (i < N_NODES * WIDTH) {
        float d = fmaxf(g_deg[i >> 6], 1.f);
        g_z[i] = fmaxf(g_agg[i] / d + g_zbase[i], 0.f);
    }
}

// ---------------------------------------------------------------------------
// out = z @ fc2_w + fc2_b : warp per node
// ---------------------------------------------------------------------------
__global__ __launch_bounds__(256) void out_kernel(const float* __restrict__ w,
                                                  const float* __restrict__ b,
                                                  float* __restrict__ out) {
    const int n = blockIdx.x * 8 + (threadIdx.x >> 5);
    const int lane = threadIdx.x & 31;
    if (n >= N_NODES) return;
    float s = g_z[n * WIDTH + lane] * w[lane] + g_z[n * WIDTH + 32 + lane] * w[32 + lane];
    #pragma unroll
    for (int off = 16; off; off >>= 1) s += __shfl_xor_sync(0xffffffffu, s, off);
    if (lane == 0) out[n] = s + b[0];
}

// ---------------------------------------------------------------------------
// Launch
// ---------------------------------------------------------------------------
extern "C" void kernel_launch(void* const* d_in, const int* in_sizes, int n_in,
                              void* d_out, int out_size) {
    const float* x      = (const float*)d_in[0];
    const int*   ei     = (const int*)  d_in[1];
    const float* ea     = (const float*)d_in[2];
    const float* fc1_w  = (const float*)d_in[3];
    const float* fc1_b  = (const float*)d_in[4];
    const float* k1_w   = (const float*)d_in[5];
    const float* k1_b   = (const float*)d_in[6];
    const float* k2_w   = (const float*)d_in[7];
    const float* k2_b   = (const float*)d_in[8];
    const float* k3_w   = (const float*)d_in[9];
    const float* k3_b   = (const float*)d_in[10];
    const float* root_w = (const float*)d_in[11];
    const float* conv_b = (const float*)d_in[12];
    const float* fc2_w  = (const float*)d_in[13];
    const float* fc2_b  = (const float*)d_in[14];
    const int* src = ei;
    const int* dst = ei + N_EDGES;
    float* out = (float*)d_out;

    __half* k2t_p; cudaGetSymbolAddress((void**)&k2t_p, g_k2t);
    __half* k3t_p; cudaGetSymbolAddress((void**)&k3t_p, g_k3t);

    cudaFuncSetAttribute(gemm_f16<0>, cudaFuncAttributeMaxDynamicSharedMemorySize, G_SMEM_BYTES);
    cudaFuncSetAttribute(gemm_f16<1>, cudaFuncAttributeMaxDynamicSharedMemorySize, G_SMEM_BYTES);

    transpose_h<<<dim3(32, 32),  dim3(32, 8)>>>(k2_w, k2t_p, KW, KW);
    transpose_h<<<dim3(32, 128), dim3(32, 8)>>>(k3_w, k3t_p, KW, WIDTH * WIDTH);
    h1_kernel<<<N_EDGES / 16, 256>>>(ea, k1_w, k1_b);
    gemm_f16<0><<<dim3(KW / 128, (N_EDGES + 127) / 128), 256, G_SMEM_BYTES>>>(k2_b);
    gemm_f16<1><<<dim3((WIDTH * WIDTH) / 128, (N_EDGES + 127) / 128), 256, G_SMEM_BYTES>>>(k3_b);
    deg_zero<<<(N_NODES + 255) / 256, 256>>>();
    deg_count<<<(N_EDGES + 255) / 256, 256>>>(dst);
    z0_kernel<<<(N_NODES * WIDTH) / 256, 256>>>(x, fc1_w, fc1_b);
    for (int it = 0; it < DEPTH; it++) {
        zbase_kernel<<<N_NODES / 4, 256>>>(root_w, conv_b);
        msg_kernel<<<(N_EDGES + 7) / 8, 256>>>(src, dst);
        update_kernel<<<(N_NODES * WIDTH) / 256, 256>>>();
    }
    out_kernel<<<(N_NODES + 7) / 8, 256>>>(fc2_w, fc2_b, out);
}